// round 2
// baseline (speedup 1.0000x reference)
#include <cuda_runtime.h>
#include <math.h>

// Problem constants
#define B_ 4
#define N_ 4096     // seq len = 64*64
#define D_ 64       // attention feature dim (H or W)
#define PAD 68      // smem row pitch (floats), keeps float4 alignment, 68%32=4
#define HW_ (64*64)
#define ELEMS (B_*64*64*64)
#define NC_ 19

// Scratch (no allocations allowed)
__device__ float g_q[B_*N_*D_];
__device__ float g_v[B_*N_*D_];
__device__ float g_o[B_*N_*D_];
__device__ float g_x1[ELEMS];
__device__ float g_p[B_*HW_];

__device__ __forceinline__ float sigmoidf_(float x) {
    return 1.f / (1.f + __expf(-x));
}

// ---------------------------------------------------------------------------
// q/v projection with layout gather.
// LAYOUT 0 (height pass): x[b, s, d] = feature[b, d, w, c], s = w*64 + c
// LAYOUT 1 (width  pass): x[b, s, d] = g_x1[b, h, d, c],    s = h*64 + c
// q = x @ wq + bq ; v = x @ wv + bv ; both written [b, s, d] row-major.
// ---------------------------------------------------------------------------
template<int LAYOUT>
__global__ __launch_bounds__(256) void qv_kernel(
    const float* __restrict__ src,
    const float* __restrict__ wq, const float* __restrict__ bq,
    const float* __restrict__ wv, const float* __restrict__ bv)
{
    extern __shared__ float sm[];
    float* sXt = sm;              // [k][r]  (transposed x tile)
    float* sWq = sm + D_*PAD;     // [k][col]
    float* sWv = sm + 2*D_*PAD;   // [k][col]

    const float* x = (LAYOUT == 0) ? src : (const float*)g_x1;
    int b = blockIdx.y, s0 = blockIdx.x * 64, tid = threadIdx.x;

    // Load weights (vectorized, conflict-free)
    for (int i = tid; i < 64*16; i += 256) {
        int k = i >> 4, c4 = (i & 15) * 4;
        float4 a  = *(const float4*)&wq[k*64 + c4];
        float4 bb = *(const float4*)&wv[k*64 + c4];
        *(float4*)&sWq[k*PAD + c4] = a;
        *(float4*)&sWv[k*PAD + c4] = bb;
    }
    // Load x tile transposed. Consecutive tid -> consecutive r -> consecutive c
    // in gmem (coalesced) and consecutive smem addresses (conflict-free).
    for (int i = tid; i < 64*64; i += 256) {
        int d = i >> 6, r = i & 63;
        int s = s0 + r;
        int idx;
        if (LAYOUT == 0) { int w = s >> 6, c = s & 63; idx = ((b*64 + d)*64 + w)*64 + c; }
        else             { int h = s >> 6, c = s & 63; idx = ((b*64 + h)*64 + d)*64 + c; }
        sXt[d*PAD + r] = x[idx];
    }
    __syncthreads();

    int ty = tid >> 4, tx = tid & 15;
    float qa[4][4] = {{0.f}}, va[4][4] = {{0.f}};

    #pragma unroll 4
    for (int k = 0; k < 64; k++) {
        float4 xr  = *(const float4*)&sXt[k*PAD + ty*4];
        float4 wqc = *(const float4*)&sWq[k*PAD + tx*4];
        float4 wvc = *(const float4*)&sWv[k*PAD + tx*4];
        float xa[4]  = {xr.x, xr.y, xr.z, xr.w};
        float wqa[4] = {wqc.x, wqc.y, wqc.z, wqc.w};
        float wva[4] = {wvc.x, wvc.y, wvc.z, wvc.w};
        #pragma unroll
        for (int i = 0; i < 4; i++)
            #pragma unroll
            for (int j = 0; j < 4; j++) {
                qa[i][j] += xa[i] * wqa[j];
                va[i][j] += xa[i] * wva[j];
            }
    }

    float4 bq4 = *(const float4*)&bq[tx*4];
    float4 bv4 = *(const float4*)&bv[tx*4];
    float bqa[4] = {bq4.x, bq4.y, bq4.z, bq4.w};
    float bva[4] = {bv4.x, bv4.y, bv4.z, bv4.w};

    #pragma unroll
    for (int i = 0; i < 4; i++) {
        int s = s0 + ty*4 + i;
        float4 qo = make_float4(qa[i][0]+bqa[0], qa[i][1]+bqa[1],
                                qa[i][2]+bqa[2], qa[i][3]+bqa[3]);
        float4 vo = make_float4(va[i][0]+bva[0], va[i][1]+bva[1],
                                va[i][2]+bva[2], va[i][3]+bva[3]);
        *(float4*)&g_q[(b*N_ + s)*D_ + tx*4] = qo;
        *(float4*)&g_v[(b*N_ + s)*D_ + tx*4] = vo;
    }
}

// ---------------------------------------------------------------------------
// Flash-style sigmoid attention (no normalization needed):
//   o[s,:] = sum_m sigmoid(q[s]·q[m] / 8) * v[m,:]
// Block: 64 query rows x full d=64, loop over 64-row K/V tiles.
// ---------------------------------------------------------------------------
__global__ __launch_bounds__(256) void attn_kernel()
{
    extern __shared__ float sm[];
    float* sQt = sm;              // [k][r]  q tile transposed
    float* sKt = sm + D_*PAD;     // [k][m]  k tile transposed
    float* sV  = sm + 2*D_*PAD;   // [m][d]  v tile natural
    float* sSt = sm + 3*D_*PAD;   // [m][r]  scores transposed

    int b = blockIdx.y, s0 = blockIdx.x * 64, tid = threadIdx.x;

    // Load Q tile (coalesced float4 gmem reads, scatter-transpose to smem)
    for (int i = tid; i < 64*16; i += 256) {
        int r = i >> 4, d4 = (i & 15) * 4;
        float4 q4 = *(const float4*)&g_q[(b*N_ + s0 + r)*D_ + d4];
        sQt[(d4+0)*PAD + r] = q4.x;
        sQt[(d4+1)*PAD + r] = q4.y;
        sQt[(d4+2)*PAD + r] = q4.z;
        sQt[(d4+3)*PAD + r] = q4.w;
    }
    __syncthreads();

    int ty = tid >> 4, tx = tid & 15;
    float oacc[4][4] = {{0.f}};

    for (int mt = 0; mt < N_; mt += 64) {
        __syncthreads();   // prev iter fully consumed sKt/sV/sSt
        for (int i = tid; i < 64*16; i += 256) {
            int r = i >> 4, d4 = (i & 15) * 4;
            float4 k4 = *(const float4*)&g_q[(b*N_ + mt + r)*D_ + d4];
            sKt[(d4+0)*PAD + r] = k4.x;
            sKt[(d4+1)*PAD + r] = k4.y;
            sKt[(d4+2)*PAD + r] = k4.z;
            sKt[(d4+3)*PAD + r] = k4.w;
            float4 v4 = *(const float4*)&g_v[(b*N_ + mt + r)*D_ + d4];
            *(float4*)&sV[r*PAD + d4] = v4;
        }
        __syncthreads();

        // S = Q Kᵀ  (4x4 micro-tile per thread, float4 smem loads)
        float sacc[4][4] = {{0.f}};
        #pragma unroll 4
        for (int k = 0; k < 64; k++) {
            float4 q4 = *(const float4*)&sQt[k*PAD + ty*4];
            float4 k4 = *(const float4*)&sKt[k*PAD + tx*4];
            float qr[4] = {q4.x, q4.y, q4.z, q4.w};
            float kc[4] = {k4.x, k4.y, k4.z, k4.w};
            #pragma unroll
            for (int i = 0; i < 4; i++)
                #pragma unroll
                for (int j = 0; j < 4; j++)
                    sacc[i][j] += qr[i] * kc[j];
        }
        // sigmoid + transpose-store to smem (sSt[m][r])
        #pragma unroll
        for (int j = 0; j < 4; j++)
            #pragma unroll
            for (int i = 0; i < 4; i++)
                sSt[(tx*4+j)*PAD + ty*4 + i] = sigmoidf_(sacc[i][j] * 0.125f);
        __syncthreads();

        // O += S V
        #pragma unroll 4
        for (int m = 0; m < 64; m++) {
            float4 s4 = *(const float4*)&sSt[m*PAD + ty*4];
            float4 v4 = *(const float4*)&sV[m*PAD + tx*4];
            float sr[4] = {s4.x, s4.y, s4.z, s4.w};
            float vc[4] = {v4.x, v4.y, v4.z, v4.w};
            #pragma unroll
            for (int i = 0; i < 4; i++)
                #pragma unroll
                for (int j = 0; j < 4; j++)
                    oacc[i][j] += sr[i] * vc[j];
        }
    }

    #pragma unroll
    for (int i = 0; i < 4; i++) {
        float4 oo = make_float4(oacc[i][0], oacc[i][1], oacc[i][2], oacc[i][3]);
        *(float4*)&g_o[(b*N_ + s0 + ty*4 + i)*D_ + tx*4] = oo;
    }
}

// x1 = feature + h_gate * attn_h   (attn_h stored [b, w*64+c, h])
__global__ void x1_kernel(const float* __restrict__ feature,
                          const float* __restrict__ hgate)
{
    int idx = blockIdx.x * blockDim.x + threadIdx.x;
    if (idx >= ELEMS) return;
    float hg = hgate[0];
    int c = idx & 63, w = (idx >> 6) & 63, h = (idx >> 12) & 63, b = idx >> 18;
    g_x1[idx] = feature[idx] + hg * g_o[(b*N_ + w*64 + c)*D_ + h];
}

// p[pixel] = (1 - sigmoid(predict)) @ conv_w + conv_b
__global__ void p_kernel(const float* __restrict__ predict,
                         const float* __restrict__ cw,
                         const float* __restrict__ cb)
{
    int pix = blockIdx.x * blockDim.x + threadIdx.x;
    if (pix >= B_*HW_) return;
    float acc = cb[0];
    #pragma unroll
    for (int k = 0; k < NC_; k++)
        acc += (1.f - sigmoidf_(predict[pix*NC_ + k])) * cw[k];
    g_p[pix] = acc;
}

// out = p * (feature + x1 + w_gate * attn_w)   (attn_w stored [b, h*64+c, w])
__global__ void final_kernel(const float* __restrict__ feature,
                             const float* __restrict__ wgate,
                             float* __restrict__ out)
{
    int idx = blockIdx.x * blockDim.x + threadIdx.x;
    if (idx >= ELEMS) return;
    float wg = wgate[0];
    int c = idx & 63, w = (idx >> 6) & 63, h = (idx >> 12) & 63, b = idx >> 18;
    float attw = g_o[(b*N_ + h*64 + c)*D_ + w];
    out[idx] = g_p[idx >> 6] * (feature[idx] + g_x1[idx] + wg * attw);
}

extern "C" void kernel_launch(void* const* d_in, const int* in_sizes, int n_in,
                              void* d_out, int out_size)
{
    const float* feature = (const float*)d_in[0];
    const float* predict = (const float*)d_in[1];
    const float* hq_w = (const float*)d_in[2];
    const float* hq_b = (const float*)d_in[3];
    const float* hv_w = (const float*)d_in[4];
    const float* hv_b = (const float*)d_in[5];
    const float* wq_w = (const float*)d_in[6];
    const float* wq_b = (const float*)d_in[7];
    const float* wv_w = (const float*)d_in[8];
    const float* wv_b = (const float*)d_in[9];
    const float* h_gate = (const float*)d_in[10];
    const float* w_gate = (const float*)d_in[11];
    const float* conv_w = (const float*)d_in[12];
    const float* conv_b = (const float*)d_in[13];
    float* out = (float*)d_out;

    const int qv_smem = 3 * D_ * PAD * (int)sizeof(float);   // 52224 B
    const int at_smem = 4 * D_ * PAD * (int)sizeof(float);   // 69632 B
    cudaFuncSetAttribute(qv_kernel<0>, cudaFuncAttributeMaxDynamicSharedMemorySize, qv_smem);
    cudaFuncSetAttribute(qv_kernel<1>, cudaFuncAttributeMaxDynamicSharedMemorySize, qv_smem);
    cudaFuncSetAttribute(attn_kernel,  cudaFuncAttributeMaxDynamicSharedMemorySize, at_smem);

    dim3 g64(N_/64, B_);

    // Pass 1: height attention
    qv_kernel<0><<<g64, 256, qv_smem>>>(feature, hq_w, hq_b, hv_w, hv_b);
    attn_kernel<<<g64, 256, at_smem>>>();
    x1_kernel<<<ELEMS/256, 256>>>(feature, h_gate);

    // Pass 2: width attention (reads g_x1 internally)
    qv_kernel<1><<<g64, 256, qv_smem>>>(nullptr, wq_w, wq_b, wv_w, wv_b);
    attn_kernel<<<g64, 256, at_smem>>>();

    // Gate + output
    p_kernel<<<(B_*HW_ + 255)/256, 256>>>(predict, conv_w, conv_b);
    final_kernel<<<ELEMS/256, 256>>>(feature, w_gate, out);
}

// round 4
// speedup vs baseline: 2.6884x; 2.6884x over previous
#include <cuda_runtime.h>
#include <cuda_bf16.h>
#include <cstdint>

#define B_ 4
#define N_ 4096
#define D_ 64
#define PAD 68
#define HW_ (64*64)
#define ELEMS (B_*64*64*64)
#define NC_ 19

// Scratch
__device__ float g_o[B_*N_*D_];
__device__ float g_x1[ELEMS];
__device__ float g_p[B_*HW_];
__device__ float g_vsum[B_*D_];
// bf16 split operands, packed bf16x2 words, natural layout [b][s][d]
__device__ unsigned g_qh[B_*N_*D_/2];
__device__ unsigned g_ql[B_*N_*D_/2];
__device__ unsigned g_vh[B_*N_*D_/2];
__device__ unsigned g_vl[B_*N_*D_/2];

// ---------------------------------------------------------------------------
__device__ __forceinline__ float sigmoidf_(float x) {
    return __fdividef(1.f, 1.f + __expf(-x));
}
__device__ __forceinline__ uint32_t smem_u32(const void* p) {
    uint32_t a;
    asm("{ .reg .u64 t; cvta.to.shared.u64 t, %1; cvt.u32.u64 %0, t; }" : "=r"(a) : "l"(p));
    return a;
}
__device__ __forceinline__ void split2(float a, float b, unsigned &wh, unsigned &wl) {
    __nv_bfloat162 h = __floats2bfloat162_rn(a, b);
    float ra = a - __bfloat162float(h.x);
    float rb = b - __bfloat162float(h.y);
    __nv_bfloat162 l = __floats2bfloat162_rn(ra, rb);
    wh = *reinterpret_cast<unsigned*>(&h);
    wl = *reinterpret_cast<unsigned*>(&l);
}
__device__ __forceinline__ unsigned packbf(float a, float b) {
    __nv_bfloat162 h = __floats2bfloat162_rn(a, b);
    return *reinterpret_cast<unsigned*>(&h);
}
__device__ __forceinline__ void ldsm4(uint32_t* r, uint32_t addr) {
    asm volatile("ldmatrix.sync.aligned.m8n8.x4.shared.b16 {%0,%1,%2,%3}, [%4];"
                 : "=r"(r[0]), "=r"(r[1]), "=r"(r[2]), "=r"(r[3]) : "r"(addr));
}
__device__ __forceinline__ void ldsm4t(uint32_t* r, uint32_t addr) {
    asm volatile("ldmatrix.sync.aligned.m8n8.x4.trans.shared.b16 {%0,%1,%2,%3}, [%4];"
                 : "=r"(r[0]), "=r"(r[1]), "=r"(r[2]), "=r"(r[3]) : "r"(addr));
}
__device__ __forceinline__ void mma16816(float* c, const uint32_t* a,
                                         uint32_t b0, uint32_t b1) {
    asm volatile("mma.sync.aligned.m16n8k16.row.col.f32.bf16.bf16.f32 "
                 "{%0,%1,%2,%3}, {%4,%5,%6,%7}, {%8,%9}, {%0,%1,%2,%3};"
                 : "+f"(c[0]), "+f"(c[1]), "+f"(c[2]), "+f"(c[3])
                 : "r"(a[0]), "r"(a[1]), "r"(a[2]), "r"(a[3]), "r"(b0), "r"(b1));
}

// ---------------------------------------------------------------------------
// q/v projection + bf16 hi/lo split. q and v both natural [b][s][d].
// LAYOUT 0: x[b,s,d] = feature[b,d,w,c], s=w*64+c
// LAYOUT 1: x[b,s,d] = g_x1[b,h,d,c],   s=h*64+c
// ---------------------------------------------------------------------------
template<int LAYOUT>
__global__ __launch_bounds__(256) void qv_kernel(
    const float* __restrict__ src,
    const float* __restrict__ wq, const float* __restrict__ bq,
    const float* __restrict__ wv, const float* __restrict__ bv)
{
    extern __shared__ float sm[];
    float* sXt = sm;
    float* sWq = sm + D_*PAD;
    float* sWv = sm + 2*D_*PAD;

    const float* x = (LAYOUT == 0) ? src : (const float*)g_x1;
    int b = blockIdx.y, s0 = blockIdx.x * 64, tid = threadIdx.x;

    for (int i = tid; i < 64*16; i += 256) {
        int k = i >> 4, c4 = (i & 15) * 4;
        *(float4*)&sWq[k*PAD + c4] = *(const float4*)&wq[k*64 + c4];
        *(float4*)&sWv[k*PAD + c4] = *(const float4*)&wv[k*64 + c4];
    }
    for (int i = tid; i < 64*64; i += 256) {
        int d = i >> 6, r = i & 63;
        int s = s0 + r, idx;
        if (LAYOUT == 0) { int w = s >> 6, c = s & 63; idx = ((b*64 + d)*64 + w)*64 + c; }
        else             { int h = s >> 6, c = s & 63; idx = ((b*64 + h)*64 + d)*64 + c; }
        sXt[d*PAD + r] = x[idx];
    }
    __syncthreads();

    int ty = tid >> 4, tx = tid & 15;
    float qa[4][4] = {{0.f}}, va[4][4] = {{0.f}};

    #pragma unroll 4
    for (int k = 0; k < 64; k++) {
        float4 xr  = *(const float4*)&sXt[k*PAD + ty*4];
        float4 wqc = *(const float4*)&sWq[k*PAD + tx*4];
        float4 wvc = *(const float4*)&sWv[k*PAD + tx*4];
        float xa[4]  = {xr.x, xr.y, xr.z, xr.w};
        float wqa[4] = {wqc.x, wqc.y, wqc.z, wqc.w};
        float wva[4] = {wvc.x, wvc.y, wvc.z, wvc.w};
        #pragma unroll
        for (int i = 0; i < 4; i++)
            #pragma unroll
            for (int j = 0; j < 4; j++) {
                qa[i][j] += xa[i] * wqa[j];
                va[i][j] += xa[i] * wva[j];
            }
    }

    float4 bq4 = *(const float4*)&bq[tx*4];
    float4 bv4 = *(const float4*)&bv[tx*4];
    float bqa[4] = {bq4.x, bq4.y, bq4.z, bq4.w};
    float bva[4] = {bv4.x, bv4.y, bv4.z, bv4.w};

    #pragma unroll
    for (int i = 0; i < 4; i++) {
        int s = s0 + ty*4 + i;
        unsigned base = (unsigned)((b*N_ + s)*32 + tx*2);
        unsigned wh01, wl01, wh23, wl23;
        split2(qa[i][0]+bqa[0], qa[i][1]+bqa[1], wh01, wl01);
        split2(qa[i][2]+bqa[2], qa[i][3]+bqa[3], wh23, wl23);
        g_qh[base] = wh01; g_qh[base+1] = wh23;
        g_ql[base] = wl01; g_ql[base+1] = wl23;
        split2(va[i][0]+bva[0], va[i][1]+bva[1], wh01, wl01);
        split2(va[i][2]+bva[2], va[i][3]+bva[3], wh23, wl23);
        g_vh[base] = wh01; g_vh[base+1] = wh23;
        g_vl[base] = wl01; g_vl[base+1] = wl23;
    }
}

// vsum[b][d] = sum_s v[b][s][d]   (exact from hi+lo)
__global__ __launch_bounds__(256) void vsum_kernel()
{
    int b = blockIdx.x, tid = threadIdx.x;
    int d = tid & 63, chunk = tid >> 6;
    int w = d >> 1, hi = d & 1;
    __shared__ float red[256];
    float acc = 0.f;
    for (int s = chunk*1024; s < chunk*1024 + 1024; s++) {
        unsigned wh_ = g_vh[(b*N_ + s)*32 + w];
        unsigned wl_ = g_vl[(b*N_ + s)*32 + w];
        __nv_bfloat162 h2 = *reinterpret_cast<__nv_bfloat162*>(&wh_);
        __nv_bfloat162 l2 = *reinterpret_cast<__nv_bfloat162*>(&wl_);
        acc += hi ? (__bfloat162float(h2.y) + __bfloat162float(l2.y))
                  : (__bfloat162float(h2.x) + __bfloat162float(l2.x));
    }
    red[tid] = acc;
    __syncthreads();
    if (chunk == 0)
        g_vsum[b*64 + d] = red[d] + red[64+d] + red[128+d] + red[192+d];
}

// ---------------------------------------------------------------------------
// HMMA sigmoid attention.  o = sigmoid(q qT/8) v
//   = sum (sig-0.5) v + 0.5 vsum
// CTA: 128 q rows, 256 thr (8 warps: 4 m x 2 n). k-tiles of 128.
// QK: 3-term hi/lo split. SV: (s-0.5) single bf16 x V hi/lo (2 terms).
// ---------------------------------------------------------------------------
#define SQH_OFF 0
#define SQL_OFF 16384
#define SKH_OFF 32768
#define SKL_OFF 49152
#define SVH_OFF 65536
#define SVL_OFF 81920
#define ATT_SMEM 98304

__global__ __launch_bounds__(256, 1) void attn_mma()
{
    extern __shared__ char smem[];
    const uint32_t sb = smem_u32(smem);
    const int tid = threadIdx.x, lane = tid & 31, wid = tid >> 5;
    const int wm = wid >> 1, wn = wid & 1;
    const int b = blockIdx.y, s0 = blockIdx.x * 128;
    const int g = lane >> 3, rr = lane & 7;

    // Q tile (hi/lo), swizzled rows of 128B
    for (int i = tid; i < 2048; i += 256) {
        int row = i >> 4, c8 = (i & 15) * 8;
        uint32_t a = (uint32_t)(row*128 + (c8 ^ ((row & 7) << 4)));
        int gi = (b*N_ + s0 + row)*16 + (i & 15);
        *(uint2*)(smem + SQH_OFF + a) = ((const uint2*)g_qh)[gi];
        *(uint2*)(smem + SQL_OFF + a) = ((const uint2*)g_ql)[gi];
    }

    float oacc[2][8][4];
    #pragma unroll
    for (int mi = 0; mi < 2; mi++)
        #pragma unroll
        for (int j = 0; j < 8; j++)
            #pragma unroll
            for (int q = 0; q < 4; q++) oacc[mi][j][q] = 0.f;

    for (int t = 0; t < 32; t++) {
        const int mt = t << 7;
        __syncthreads();
        for (int i = tid; i < 2048; i += 256) {
            int row = i >> 4, c8 = (i & 15) * 8;
            uint32_t a = (uint32_t)(row*128 + (c8 ^ ((row & 7) << 4)));
            int gi = (b*N_ + mt + row)*16 + (i & 15);
            *(uint2*)(smem + SKH_OFF + a) = ((const uint2*)g_qh)[gi];
            *(uint2*)(smem + SKL_OFF + a) = ((const uint2*)g_ql)[gi];
            *(uint2*)(smem + SVH_OFF + a) = ((const uint2*)g_vh)[gi];
            *(uint2*)(smem + SVL_OFF + a) = ((const uint2*)g_vl)[gi];
        }
        __syncthreads();

        // ---- S = Q Kᵀ (hi/lo 3-term) ----
        float sacc[2][8][4];
        #pragma unroll
        for (int mi = 0; mi < 2; mi++)
            #pragma unroll
            for (int j = 0; j < 8; j++)
                #pragma unroll
                for (int q = 0; q < 4; q++) sacc[mi][j][q] = 0.f;

        #pragma unroll
        for (int kk = 0; kk < 4; kk++) {
            uint32_t aqh[2][4], aql[2][4];
            #pragma unroll
            for (int mi = 0; mi < 2; mi++) {
                int row = wm*32 + mi*16 + rr + ((g & 1) << 3);
                uint32_t cb = (uint32_t)(kk*32 + ((g >> 1) << 4));
                uint32_t ad = sb + (uint32_t)(row*128) + (cb ^ ((row & 7) << 4));
                ldsm4(aqh[mi], ad + SQH_OFF);
                ldsm4(aql[mi], ad + SQL_OFF);
            }
            #pragma unroll
            for (int p = 0; p < 4; p++) {
                int key = wn*64 + p*16 + rr + ((g >> 1) << 3);
                uint32_t cb = (uint32_t)(kk*32 + ((g & 1) << 4));
                uint32_t ad = sb + (uint32_t)(key*128) + (cb ^ ((key & 7) << 4));
                uint32_t bh[4], bl[4];
                ldsm4(bh, ad + SKH_OFF);
                ldsm4(bl, ad + SKL_OFF);
                #pragma unroll
                for (int mi = 0; mi < 2; mi++) {
                    mma16816(sacc[mi][2*p],   aqh[mi], bh[0], bh[1]);
                    mma16816(sacc[mi][2*p+1], aqh[mi], bh[2], bh[3]);
                    mma16816(sacc[mi][2*p],   aqh[mi], bl[0], bl[1]);
                    mma16816(sacc[mi][2*p+1], aqh[mi], bl[2], bl[3]);
                    mma16816(sacc[mi][2*p],   aql[mi], bh[0], bh[1]);
                    mma16816(sacc[mi][2*p+1], aql[mi], bh[2], bh[3]);
                }
            }
        }

        // ---- sigmoid, centered ----
        #pragma unroll
        for (int mi = 0; mi < 2; mi++)
            #pragma unroll
            for (int j = 0; j < 8; j++)
                #pragma unroll
                for (int q = 0; q < 4; q++)
                    sacc[mi][j][q] = sigmoidf_(sacc[mi][j][q] * 0.125f) - 0.5f;

        // ---- O += (S-0.5) V  (V hi/lo, 2 terms) ----
        #pragma unroll
        for (int kk = 0; kk < 4; kk++) {
            uint32_t as[2][4];
            #pragma unroll
            for (int mi = 0; mi < 2; mi++) {
                as[mi][0] = packbf(sacc[mi][2*kk][0],   sacc[mi][2*kk][1]);
                as[mi][1] = packbf(sacc[mi][2*kk][2],   sacc[mi][2*kk][3]);
                as[mi][2] = packbf(sacc[mi][2*kk+1][0], sacc[mi][2*kk+1][1]);
                as[mi][3] = packbf(sacc[mi][2*kk+1][2], sacc[mi][2*kk+1][3]);
            }
            const int K0 = wn*64 + kk*16;
            #pragma unroll
            for (int p = 0; p < 4; p++) {
                int key = K0 + rr + ((g & 1) << 3);
                uint32_t cb = (uint32_t)(p*32 + ((g >> 1) << 4));
                uint32_t ad = sb + (uint32_t)(key*128) + (cb ^ ((key & 7) << 4));
                uint32_t bh[4], bl[4];
                ldsm4t(bh, ad + SVH_OFF);
                ldsm4t(bl, ad + SVL_OFF);
                #pragma unroll
                for (int mi = 0; mi < 2; mi++) {
                    mma16816(oacc[mi][2*p],   as[mi], bh[0], bh[1]);
                    mma16816(oacc[mi][2*p+1], as[mi], bh[2], bh[3]);
                    mma16816(oacc[mi][2*p],   as[mi], bl[0], bl[1]);
                    mma16816(oacc[mi][2*p+1], as[mi], bl[2], bl[3]);
                }
            }
        }
    }

    // ---- cross-warp_n reduction + vsum correction + writeout ----
    __syncthreads();
    float* ored = (float*)(smem + SKH_OFF);   // 128x64 fp32, 32KB
    if (wn == 1) {
        #pragma unroll
        for (int mi = 0; mi < 2; mi++)
            #pragma unroll
            for (int dj = 0; dj < 8; dj++) {
                int row = wm*32 + mi*16 + (lane >> 2);
                int col = dj*8 + (lane & 3)*2;
                *(float2*)&ored[row*64 + col]     = make_float2(oacc[mi][dj][0], oacc[mi][dj][1]);
                *(float2*)&ored[(row+8)*64 + col] = make_float2(oacc[mi][dj][2], oacc[mi][dj][3]);
            }
    }
    __syncthreads();
    if (wn == 0) {
        #pragma unroll
        for (int mi = 0; mi < 2; mi++)
            #pragma unroll
            for (int dj = 0; dj < 8; dj++) {
                int row = wm*32 + mi*16 + (lane >> 2);
                int col = dj*8 + (lane & 3)*2;
                float vs0 = 0.5f * g_vsum[b*64 + col];
                float vs1 = 0.5f * g_vsum[b*64 + col + 1];
                float2 p0 = *(float2*)&ored[row*64 + col];
                float2 p1 = *(float2*)&ored[(row+8)*64 + col];
                *(float2*)&g_o[(size_t)(b*N_ + s0 + row)*64 + col] =
                    make_float2(oacc[mi][dj][0] + p0.x + vs0, oacc[mi][dj][1] + p0.y + vs1);
                *(float2*)&g_o[(size_t)(b*N_ + s0 + row + 8)*64 + col] =
                    make_float2(oacc[mi][dj][2] + p1.x + vs0, oacc[mi][dj][3] + p1.y + vs1);
            }
    }
}

// ---------------------------------------------------------------------------
__global__ void x1_kernel(const float* __restrict__ feature,
                          const float* __restrict__ hgate)
{
    int idx = blockIdx.x * blockDim.x + threadIdx.x;
    if (idx >= ELEMS) return;
    float hg = hgate[0];
    int c = idx & 63, w = (idx >> 6) & 63, h = (idx >> 12) & 63, b = idx >> 18;
    g_x1[idx] = feature[idx] + hg * g_o[(b*N_ + w*64 + c)*D_ + h];
}

__global__ void p_kernel(const float* __restrict__ predict,
                         const float* __restrict__ cw,
                         const float* __restrict__ cb)
{
    int pix = blockIdx.x * blockDim.x + threadIdx.x;
    if (pix >= B_*HW_) return;
    float acc = cb[0];
    #pragma unroll
    for (int k = 0; k < NC_; k++)
        acc += (1.f - sigmoidf_(predict[pix*NC_ + k])) * cw[k];
    g_p[pix] = acc;
}

__global__ void final_kernel(const float* __restrict__ feature,
                             const float* __restrict__ wgate,
                             float* __restrict__ out)
{
    int idx = blockIdx.x * blockDim.x + threadIdx.x;
    if (idx >= ELEMS) return;
    float wg = wgate[0];
    int c = idx & 63, w = (idx >> 6) & 63, h = (idx >> 12) & 63, b = idx >> 18;
    float attw = g_o[(b*N_ + h*64 + c)*D_ + w];
    out[idx] = g_p[idx >> 6] * (feature[idx] + g_x1[idx] + wg * attw);
}

extern "C" void kernel_launch(void* const* d_in, const int* in_sizes, int n_in,
                              void* d_out, int out_size)
{
    const float* feature = (const float*)d_in[0];
    const float* predict = (const float*)d_in[1];
    const float* hq_w = (const float*)d_in[2];
    const float* hq_b = (const float*)d_in[3];
    const float* hv_w = (const float*)d_in[4];
    const float* hv_b = (const float*)d_in[5];
    const float* wq_w = (const float*)d_in[6];
    const float* wq_b = (const float*)d_in[7];
    const float* wv_w = (const float*)d_in[8];
    const float* wv_b = (const float*)d_in[9];
    const float* h_gate = (const float*)d_in[10];
    const float* w_gate = (const float*)d_in[11];
    const float* conv_w = (const float*)d_in[12];
    const float* conv_b = (const float*)d_in[13];
    float* out = (float*)d_out;

    const int qv_smem = 3 * D_ * PAD * (int)sizeof(float);
    cudaFuncSetAttribute(qv_kernel<0>, cudaFuncAttributeMaxDynamicSharedMemorySize, qv_smem);
    cudaFuncSetAttribute(qv_kernel<1>, cudaFuncAttributeMaxDynamicSharedMemorySize, qv_smem);
    cudaFuncSetAttribute(attn_mma, cudaFuncAttributeMaxDynamicSharedMemorySize, ATT_SMEM);

    dim3 gqv(N_/64, B_);
    dim3 gat(N_/128, B_);

    // Pass 1: height attention
    qv_kernel<0><<<gqv, 256, qv_smem>>>(feature, hq_w, hq_b, hv_w, hv_b);
    vsum_kernel<<<B_, 256>>>();
    attn_mma<<<gat, 256, ATT_SMEM>>>();
    x1_kernel<<<ELEMS/256, 256>>>(feature, h_gate);

    // Pass 2: width attention
    qv_kernel<1><<<gqv, 256, qv_smem>>>(nullptr, wq_w, wq_b, wv_w, wv_b);
    vsum_kernel<<<B_, 256>>>();
    attn_mma<<<gat, 256, ATT_SMEM>>>();

    // Gate + output
    p_kernel<<<(B_*HW_ + 255)/256, 256>>>(predict, conv_w, conv_b);
    final_kernel<<<ELEMS/256, 256>>>(feature, w_gate, out);
}

// round 7
// speedup vs baseline: 4.4687x; 1.6622x over previous
#include <cuda_runtime.h>
#include <cuda_bf16.h>
#include <cstdint>

#define B_ 4
#define N_ 4096
#define D_ 64
#define PAD 68
#define HW_ (64*64)
#define ELEMS (B_*64*64*64)
#define NC_ 19

// Scratch
__device__ float g_o[B_*N_*D_];
__device__ float g_x1[ELEMS];
__device__ float g_p[B_*HW_];
__device__ float g_vsum[B_*D_];
// bf16 split operands, packed bf16x2 words, natural layout [b][s][d]
__device__ __align__(128) unsigned g_qh[B_*N_*D_/2];
__device__ __align__(128) unsigned g_ql[B_*N_*D_/2];
__device__ __align__(128) unsigned g_vh[B_*N_*D_/2];
__device__ __align__(128) unsigned g_vl[B_*N_*D_/2];

// ---------------------------------------------------------------------------
__device__ __forceinline__ float sigmoidf_(float x) {
    return __fdividef(1.f, 1.f + __expf(-x));
}
__device__ __forceinline__ uint32_t smem_u32(const void* p) {
    uint32_t a;
    asm("{ .reg .u64 t; cvta.to.shared.u64 t, %1; cvt.u32.u64 %0, t; }" : "=r"(a) : "l"(p));
    return a;
}
__device__ __forceinline__ void split2(float a, float b, unsigned &wh, unsigned &wl) {
    __nv_bfloat162 h = __floats2bfloat162_rn(a, b);
    float ra = a - __bfloat162float(h.x);
    float rb = b - __bfloat162float(h.y);
    __nv_bfloat162 l = __floats2bfloat162_rn(ra, rb);
    wh = *reinterpret_cast<unsigned*>(&h);
    wl = *reinterpret_cast<unsigned*>(&l);
}
__device__ __forceinline__ unsigned packbf(float a, float b) {
    __nv_bfloat162 h = __floats2bfloat162_rn(a, b);
    return *reinterpret_cast<unsigned*>(&h);
}
__device__ __forceinline__ void ldsm4(uint32_t* r, uint32_t addr) {
    asm volatile("ldmatrix.sync.aligned.m8n8.x4.shared.b16 {%0,%1,%2,%3}, [%4];"
                 : "=r"(r[0]), "=r"(r[1]), "=r"(r[2]), "=r"(r[3]) : "r"(addr));
}
__device__ __forceinline__ void ldsm4t(uint32_t* r, uint32_t addr) {
    asm volatile("ldmatrix.sync.aligned.m8n8.x4.trans.shared.b16 {%0,%1,%2,%3}, [%4];"
                 : "=r"(r[0]), "=r"(r[1]), "=r"(r[2]), "=r"(r[3]) : "r"(addr));
}
__device__ __forceinline__ void mma16816(float* c, const uint32_t* a,
                                         uint32_t b0, uint32_t b1) {
    asm volatile("mma.sync.aligned.m16n8k16.row.col.f32.bf16.bf16.f32 "
                 "{%0,%1,%2,%3}, {%4,%5,%6,%7}, {%8,%9}, {%0,%1,%2,%3};"
                 : "+f"(c[0]), "+f"(c[1]), "+f"(c[2]), "+f"(c[3])
                 : "r"(a[0]), "r"(a[1]), "r"(a[2]), "r"(a[3]), "r"(b0), "r"(b1));
}
__device__ __forceinline__ void cpa16(uint32_t s, const void* g) {
    asm volatile("cp.async.cg.shared.global [%0], [%1], 16;"
                 :: "r"(s), "l"(__cvta_generic_to_global(g)) : "memory");
}
#define CP_COMMIT() asm volatile("cp.async.commit_group;" ::: "memory")

// ---------------------------------------------------------------------------
// q/v projection + bf16 hi/lo split. q and v both natural [b][s][d].
// ---------------------------------------------------------------------------
template<int LAYOUT>
__global__ __launch_bounds__(256) void qv_kernel(
    const float* __restrict__ src,
    const float* __restrict__ wq, const float* __restrict__ bq,
    const float* __restrict__ wv, const float* __restrict__ bv)
{
    extern __shared__ float sm[];
    float* sXt = sm;
    float* sWq = sm + D_*PAD;
    float* sWv = sm + 2*D_*PAD;

    const float* x = (LAYOUT == 0) ? src : (const float*)g_x1;
    int b = blockIdx.y, s0 = blockIdx.x * 64, tid = threadIdx.x;

    for (int i = tid; i < 64*16; i += 256) {
        int k = i >> 4, c4 = (i & 15) * 4;
        *(float4*)&sWq[k*PAD + c4] = *(const float4*)&wq[k*64 + c4];
        *(float4*)&sWv[k*PAD + c4] = *(const float4*)&wv[k*64 + c4];
    }
    for (int i = tid; i < 64*64; i += 256) {
        int d = i >> 6, r = i & 63;
        int s = s0 + r, idx;
        if (LAYOUT == 0) { int w = s >> 6, c = s & 63; idx = ((b*64 + d)*64 + w)*64 + c; }
        else             { int h = s >> 6, c = s & 63; idx = ((b*64 + h)*64 + d)*64 + c; }
        sXt[d*PAD + r] = x[idx];
    }
    __syncthreads();

    int ty = tid >> 4, tx = tid & 15;
    float qa[4][4] = {{0.f}}, va[4][4] = {{0.f}};

    #pragma unroll 4
    for (int k = 0; k < 64; k++) {
        float4 xr  = *(const float4*)&sXt[k*PAD + ty*4];
        float4 wqc = *(const float4*)&sWq[k*PAD + tx*4];
        float4 wvc = *(const float4*)&sWv[k*PAD + tx*4];
        float xa[4]  = {xr.x, xr.y, xr.z, xr.w};
        float wqa[4] = {wqc.x, wqc.y, wqc.z, wqc.w};
        float wva[4] = {wvc.x, wvc.y, wvc.z, wvc.w};
        #pragma unroll
        for (int i = 0; i < 4; i++)
            #pragma unroll
            for (int j = 0; j < 4; j++) {
                qa[i][j] += xa[i] * wqa[j];
                va[i][j] += xa[i] * wva[j];
            }
    }

    float4 bq4 = *(const float4*)&bq[tx*4];
    float4 bv4 = *(const float4*)&bv[tx*4];
    float bqa[4] = {bq4.x, bq4.y, bq4.z, bq4.w};
    float bva[4] = {bv4.x, bv4.y, bv4.z, bv4.w};

    #pragma unroll
    for (int i = 0; i < 4; i++) {
        int s = s0 + ty*4 + i;
        unsigned base = (unsigned)((b*N_ + s)*32 + tx*2);
        unsigned wh01, wl01, wh23, wl23;
        split2(qa[i][0]+bqa[0], qa[i][1]+bqa[1], wh01, wl01);
        split2(qa[i][2]+bqa[2], qa[i][3]+bqa[3], wh23, wl23);
        g_qh[base] = wh01; g_qh[base+1] = wh23;
        g_ql[base] = wl01; g_ql[base+1] = wl23;
        split2(va[i][0]+bva[0], va[i][1]+bva[1], wh01, wl01);
        split2(va[i][2]+bva[2], va[i][3]+bva[3], wh23, wl23);
        g_vh[base] = wh01; g_vh[base+1] = wh23;
        g_vl[base] = wl01; g_vl[base+1] = wl23;
    }
}

// vsum[b][d] = sum_s v[b][s][d]  (exact from hi+lo, fp32 accumulate)
__global__ __launch_bounds__(512) void vsum_kernel()
{
    int b = blockIdx.x, tid = threadIdx.x;
    int d = tid & 63, chunk = tid >> 6;       // 8 chunks of 512 rows
    int w = d >> 1, hi = d & 1;
    __shared__ float red[512];
    float acc = 0.f;
    for (int s = chunk*512; s < chunk*512 + 512; s++) {
        unsigned wh_ = g_vh[(b*N_ + s)*32 + w];
        unsigned wl_ = g_vl[(b*N_ + s)*32 + w];
        __nv_bfloat162 h2 = *reinterpret_cast<__nv_bfloat162*>(&wh_);
        __nv_bfloat162 l2 = *reinterpret_cast<__nv_bfloat162*>(&wl_);
        acc += hi ? (__bfloat162float(h2.y) + __bfloat162float(l2.y))
                  : (__bfloat162float(h2.x) + __bfloat162float(l2.x));
    }
    red[tid] = acc;
    __syncthreads();
    if (chunk == 0) {
        float s = 0.f;
        #pragma unroll
        for (int k = 0; k < 8; k++) s += red[d + 64*k];
        g_vsum[b*64 + d] = s;
    }
}

// ---------------------------------------------------------------------------
// HMMA sigmoid attention, double-buffered cp.async, fused epilogue.
// o = sum (sig(qk/8)-0.5) v_hi + 0.5 vsum_exact
// QK: Qh x (Kh + Kl)  (2 terms).  SV: (s-0.5) bf16 x Vh  (1 term).
// ---------------------------------------------------------------------------
#define QH_OFF 0
#define BUF0 16384
#define BUFSZ 49152            // KH 16K | KL 16K | VH 16K
#define ATT_SMEM (16384 + 2*BUFSZ)   // 114688

__device__ __forceinline__ void load_tile(uint32_t sbuf, int b, int mt, int tid)
{
    const char* pQH = (const char*)g_qh;
    const char* pQL = (const char*)g_ql;
    const char* pVH = (const char*)g_vh;
    #pragma unroll
    for (int j = 0; j < 12; j++) {
        const char* src = (j < 4) ? pQH : ((j < 8) ? pQL : pVH);
        int rem = tid + (j & 3)*256;            // 0..1023
        int r = rem >> 3, c = (rem & 7)*16;
        // row stride = 64 bf16 = 128 BYTES  (R6 bug: used *64)
        cpa16(sbuf + (uint32_t)((j >> 2)*16384 + r*128 + (c ^ ((r & 7) << 4))),
              src + (size_t)(b*N_ + mt + r)*128 + c);
    }
}

__global__ __launch_bounds__(256, 1) void attn_mma()
{
    extern __shared__ char smem[];
    const uint32_t sb = smem_u32(smem);
    const int tid = threadIdx.x, lane = tid & 31, wid = tid >> 5;
    const int wm = wid >> 1, wn = wid & 1;
    const int b = blockIdx.y, s0 = blockIdx.x * 128;
    const int g = lane >> 3, rr = lane & 7;

    // prologue: Q-hi tile + K/V tile 0, one cp.async group
    {
        const char* pQH = (const char*)g_qh;
        #pragma unroll
        for (int j = 0; j < 4; j++) {
            int rem = tid + j*256;
            int r = rem >> 3, c = (rem & 7)*16;
            cpa16(sb + QH_OFF + (uint32_t)(r*128 + (c ^ ((r & 7) << 4))),
                  pQH + (size_t)(b*N_ + s0 + r)*128 + c);
        }
    }
    load_tile(sb + BUF0, b, 0, tid);
    CP_COMMIT();

    uint32_t qfh[2][4][4];        // Q-hi fragments [mi][kk][4], live whole kernel
    float oacc[2][8][4];
    #pragma unroll
    for (int mi = 0; mi < 2; mi++)
        #pragma unroll
        for (int j = 0; j < 8; j++)
            #pragma unroll
            for (int q = 0; q < 4; q++) oacc[mi][j][q] = 0.f;

    for (int t = 0; t < 32; t++) {
        if (t < 31) {
            load_tile(sb + BUF0 + (uint32_t)(((t+1) & 1)*BUFSZ), b, (t+1) << 7, tid);
            CP_COMMIT();
            asm volatile("cp.async.wait_group 1;" ::: "memory");
        } else {
            asm volatile("cp.async.wait_group 0;" ::: "memory");
        }
        __syncthreads();

        const uint32_t kb = sb + BUF0 + (uint32_t)((t & 1)*BUFSZ);

        if (t == 0) {
            #pragma unroll
            for (int kk = 0; kk < 4; kk++)
                #pragma unroll
                for (int mi = 0; mi < 2; mi++) {
                    int row = wm*32 + mi*16 + rr + ((g & 1) << 3);
                    uint32_t cb = (uint32_t)(kk*32 + ((g >> 1) << 4));
                    ldsm4(qfh[mi][kk], sb + QH_OFF + (uint32_t)(row*128) + (cb ^ ((row & 7) << 4)));
                }
        }

        // fused: per 16-key group -> QK(2-term), sigmoid, SV(1-term)
        #pragma unroll
        for (int p = 0; p < 4; p++) {
            float sacc[2][2][4];
            #pragma unroll
            for (int mi = 0; mi < 2; mi++)
                #pragma unroll
                for (int jj = 0; jj < 2; jj++)
                    #pragma unroll
                    for (int q = 0; q < 4; q++) sacc[mi][jj][q] = 0.f;

            #pragma unroll
            for (int kk = 0; kk < 4; kk++) {
                int key = wn*64 + p*16 + rr + ((g >> 1) << 3);
                uint32_t cb = (uint32_t)(kk*32 + ((g & 1) << 4));
                uint32_t ad = kb + (uint32_t)(key*128) + (cb ^ ((key & 7) << 4));
                uint32_t bh[4], bl[4];
                ldsm4(bh, ad);                // K hi
                ldsm4(bl, ad + 16384);        // K lo
                #pragma unroll
                for (int mi = 0; mi < 2; mi++) {
                    mma16816(sacc[mi][0], qfh[mi][kk], bh[0], bh[1]);
                    mma16816(sacc[mi][1], qfh[mi][kk], bh[2], bh[3]);
                    mma16816(sacc[mi][0], qfh[mi][kk], bl[0], bl[1]);
                    mma16816(sacc[mi][1], qfh[mi][kk], bl[2], bl[3]);
                }
            }

            // centered sigmoid, saturation-safe: sig(x/8) - 0.5
            uint32_t as_[2][4];
            #pragma unroll
            for (int mi = 0; mi < 2; mi++) {
                #pragma unroll
                for (int jj = 0; jj < 2; jj++)
                    #pragma unroll
                    for (int q = 0; q < 4; q++) {
                        float e = __expf(-0.125f * sacc[mi][jj][q]);
                        sacc[mi][jj][q] = __fdividef(1.f, 1.f + e) - 0.5f;
                    }
                as_[mi][0] = packbf(sacc[mi][0][0], sacc[mi][0][1]);
                as_[mi][1] = packbf(sacc[mi][0][2], sacc[mi][0][3]);
                as_[mi][2] = packbf(sacc[mi][1][0], sacc[mi][1][1]);
                as_[mi][3] = packbf(sacc[mi][1][2], sacc[mi][1][3]);
            }

            #pragma unroll
            for (int dp = 0; dp < 4; dp++) {
                int key = wn*64 + p*16 + rr + ((g & 1) << 3);
                uint32_t cb = (uint32_t)(dp*32 + ((g >> 1) << 4));
                uint32_t ad = kb + 32768u + (uint32_t)(key*128) + (cb ^ ((key & 7) << 4));
                uint32_t vh[4];
                ldsm4t(vh, ad);               // V hi (transposed)
                #pragma unroll
                for (int mi = 0; mi < 2; mi++) {
                    mma16816(oacc[mi][2*dp],   as_[mi], vh[0], vh[1]);
                    mma16816(oacc[mi][2*dp+1], as_[mi], vh[2], vh[3]);
                }
            }
        }
        __syncthreads();   // all reads of buf[t&1] done before next overwrite
    }

    // ---- cross-warp_n reduction + vsum correction + writeout ----
    float* ored = (float*)(smem + BUF0);      // 128x64 fp32, 32KB
    if (wn == 1) {
        #pragma unroll
        for (int mi = 0; mi < 2; mi++)
            #pragma unroll
            for (int dj = 0; dj < 8; dj++) {
                int row = wm*32 + mi*16 + (lane >> 2);
                int col = dj*8 + (lane & 3)*2;
                *(float2*)&ored[row*64 + col]     = make_float2(oacc[mi][dj][0], oacc[mi][dj][1]);
                *(float2*)&ored[(row+8)*64 + col] = make_float2(oacc[mi][dj][2], oacc[mi][dj][3]);
            }
    }
    __syncthreads();
    if (wn == 0) {
        #pragma unroll
        for (int mi = 0; mi < 2; mi++)
            #pragma unroll
            for (int dj = 0; dj < 8; dj++) {
                int row = wm*32 + mi*16 + (lane >> 2);
                int col = dj*8 + (lane & 3)*2;
                float vs0 = 0.5f * g_vsum[b*64 + col];
                float vs1 = 0.5f * g_vsum[b*64 + col + 1];
                float2 p0 = *(float2*)&ored[row*64 + col];
                float2 p1 = *(float2*)&ored[(row+8)*64 + col];
                *(float2*)&g_o[(size_t)(b*N_ + s0 + row)*64 + col] =
                    make_float2(oacc[mi][dj][0] + p0.x + vs0, oacc[mi][dj][1] + p0.y + vs1);
                *(float2*)&g_o[(size_t)(b*N_ + s0 + row + 8)*64 + col] =
                    make_float2(oacc[mi][dj][2] + p1.x + vs0, oacc[mi][dj][3] + p1.y + vs1);
            }
    }
}

// ---------------------------------------------------------------------------
__global__ void x1_kernel(const float* __restrict__ feature,
                          const float* __restrict__ hgate)
{
    int idx = blockIdx.x * blockDim.x + threadIdx.x;
    if (idx >= ELEMS) return;
    float hg = hgate[0];
    int c = idx & 63, w = (idx >> 6) & 63, h = (idx >> 12) & 63, b = idx >> 18;
    g_x1[idx] = feature[idx] + hg * g_o[(b*N_ + w*64 + c)*D_ + h];
}

__global__ void p_kernel(const float* __restrict__ predict,
                         const float* __restrict__ cw,
                         const float* __restrict__ cb)
{
    int pix = blockIdx.x * blockDim.x + threadIdx.x;
    if (pix >= B_*HW_) return;
    float acc = cb[0];
    #pragma unroll
    for (int k = 0; k < NC_; k++)
        acc += (1.f - sigmoidf_(predict[pix*NC_ + k])) * cw[k];
    g_p[pix] = acc;
}

__global__ void final_kernel(const float* __restrict__ feature,
                             const float* __restrict__ wgate,
                             float* __restrict__ out)
{
    int idx = blockIdx.x * blockDim.x + threadIdx.x;
    if (idx >= ELEMS) return;
    float wg = wgate[0];
    int c = idx & 63, w = (idx >> 6) & 63, h = (idx >> 12) & 63, b = idx >> 18;
    float attw = g_o[(b*N_ + h*64 + c)*D_ + w];
    out[idx] = g_p[idx >> 6] * (feature[idx] + g_x1[idx] + wg * attw);
}

extern "C" void kernel_launch(void* const* d_in, const int* in_sizes, int n_in,
                              void* d_out, int out_size)
{
    const float* feature = (const float*)d_in[0];
    const float* predict = (const float*)d_in[1];
    const float* hq_w = (const float*)d_in[2];
    const float* hq_b = (const float*)d_in[3];
    const float* hv_w = (const float*)d_in[4];
    const float* hv_b = (const float*)d_in[5];
    const float* wq_w = (const float*)d_in[6];
    const float* wq_b = (const float*)d_in[7];
    const float* wv_w = (const float*)d_in[8];
    const float* wv_b = (const float*)d_in[9];
    const float* h_gate = (const float*)d_in[10];
    const float* w_gate = (const float*)d_in[11];
    const float* conv_w = (const float*)d_in[12];
    const float* conv_b = (const float*)d_in[13];
    float* out = (float*)d_out;

    const int qv_smem = 3 * D_ * PAD * (int)sizeof(float);
    cudaFuncSetAttribute(qv_kernel<0>, cudaFuncAttributeMaxDynamicSharedMemorySize, qv_smem);
    cudaFuncSetAttribute(qv_kernel<1>, cudaFuncAttributeMaxDynamicSharedMemorySize, qv_smem);
    cudaFuncSetAttribute(attn_mma, cudaFuncAttributeMaxDynamicSharedMemorySize, ATT_SMEM);

    dim3 gqv(N_/64, B_);
    dim3 gat(N_/128, B_);

    // Pass 1: height attention
    qv_kernel<0><<<gqv, 256, qv_smem>>>(feature, hq_w, hq_b, hv_w, hv_b);
    vsum_kernel<<<B_, 512>>>();
    attn_mma<<<gat, 256, ATT_SMEM>>>();
    x1_kernel<<<ELEMS/256, 256>>>(feature, h_gate);

    // Pass 2: width attention
    qv_kernel<1><<<gqv, 256, qv_smem>>>(nullptr, wq_w, wq_b, wv_w, wv_b);
    vsum_kernel<<<B_, 512>>>();
    attn_mma<<<gat, 256, ATT_SMEM>>>();

    // Gate + output
    p_kernel<<<(B_*HW_ + 255)/256, 256>>>(predict, conv_w, conv_b);
    final_kernel<<<ELEMS/256, 256>>>(feature, w_gate, out);
}

// round 8
// speedup vs baseline: 6.5134x; 1.4576x over previous
#include <cuda_runtime.h>
#include <cuda_fp16.h>
#include <cstdint>

#define B_ 4
#define N_ 4096
#define D_ 64
#define PAD 68
#define HW_ (64*64)
#define ELEMS (B_*64*64*64)
#define NC_ 19

// Scratch
__device__ float g_o[B_*N_*D_];
__device__ float g_x1[ELEMS];
__device__ float g_p[B_*HW_];
__device__ float g_vsum[B_*D_];
// fp16 operands, packed half2 words, natural layout [b][s][d]
__device__ __align__(128) unsigned g_q16[B_*N_*D_/2];
__device__ __align__(128) unsigned g_v16[B_*N_*D_/2];

// ---------------------------------------------------------------------------
__device__ __forceinline__ float sigmoidf_(float x) {
    return __fdividef(1.f, 1.f + __expf(-x));
}
__device__ __forceinline__ uint32_t smem_u32(const void* p) {
    uint32_t a;
    asm("{ .reg .u64 t; cvta.to.shared.u64 t, %1; cvt.u32.u64 %0, t; }" : "=r"(a) : "l"(p));
    return a;
}
__device__ __forceinline__ unsigned pack2h(float a, float b) {
    __half2 h = __floats2half2_rn(a, b);
    return *reinterpret_cast<unsigned*>(&h);
}
__device__ __forceinline__ void ldsm4(uint32_t* r, uint32_t addr) {
    asm volatile("ldmatrix.sync.aligned.m8n8.x4.shared.b16 {%0,%1,%2,%3}, [%4];"
                 : "=r"(r[0]), "=r"(r[1]), "=r"(r[2]), "=r"(r[3]) : "r"(addr));
}
__device__ __forceinline__ void ldsm4t(uint32_t* r, uint32_t addr) {
    asm volatile("ldmatrix.sync.aligned.m8n8.x4.trans.shared.b16 {%0,%1,%2,%3}, [%4];"
                 : "=r"(r[0]), "=r"(r[1]), "=r"(r[2]), "=r"(r[3]) : "r"(addr));
}
__device__ __forceinline__ void mma16816(float* c, const uint32_t* a,
                                         uint32_t b0, uint32_t b1) {
    asm volatile("mma.sync.aligned.m16n8k16.row.col.f32.f16.f16.f32 "
                 "{%0,%1,%2,%3}, {%4,%5,%6,%7}, {%8,%9}, {%0,%1,%2,%3};"
                 : "+f"(c[0]), "+f"(c[1]), "+f"(c[2]), "+f"(c[3])
                 : "r"(a[0]), "r"(a[1]), "r"(a[2]), "r"(a[3]), "r"(b0), "r"(b1));
}
__device__ __forceinline__ void cpa16(uint32_t s, const void* g) {
    asm volatile("cp.async.cg.shared.global [%0], [%1], 16;"
                 :: "r"(s), "l"(__cvta_generic_to_global(g)) : "memory");
}
#define CP_COMMIT() asm volatile("cp.async.commit_group;" ::: "memory")

// ---------------------------------------------------------------------------
// q/v projection + fp16 convert. q and v both natural [b][s][d].
// LAYOUT 0: x[b,s,d] = feature[b,d,w,c], s=w*64+c
// LAYOUT 1: x[b,s,d] = g_x1[b,h,d,c],   s=h*64+c
// ---------------------------------------------------------------------------
template<int LAYOUT>
__global__ __launch_bounds__(256) void qv_kernel(
    const float* __restrict__ src,
    const float* __restrict__ wq, const float* __restrict__ bq,
    const float* __restrict__ wv, const float* __restrict__ bv)
{
    extern __shared__ float sm[];
    float* sXt = sm;
    float* sWq = sm + D_*PAD;
    float* sWv = sm + 2*D_*PAD;

    const float* x = (LAYOUT == 0) ? src : (const float*)g_x1;
    int b = blockIdx.y, s0 = blockIdx.x * 64, tid = threadIdx.x;

    for (int i = tid; i < 64*16; i += 256) {
        int k = i >> 4, c4 = (i & 15) * 4;
        *(float4*)&sWq[k*PAD + c4] = *(const float4*)&wq[k*64 + c4];
        *(float4*)&sWv[k*PAD + c4] = *(const float4*)&wv[k*64 + c4];
    }
    for (int i = tid; i < 64*64; i += 256) {
        int d = i >> 6, r = i & 63;
        int s = s0 + r, idx;
        if (LAYOUT == 0) { int w = s >> 6, c = s & 63; idx = ((b*64 + d)*64 + w)*64 + c; }
        else             { int h = s >> 6, c = s & 63; idx = ((b*64 + h)*64 + d)*64 + c; }
        sXt[d*PAD + r] = x[idx];
    }
    __syncthreads();

    int ty = tid >> 4, tx = tid & 15;
    float qa[4][4] = {{0.f}}, va[4][4] = {{0.f}};

    #pragma unroll 4
    for (int k = 0; k < 64; k++) {
        float4 xr  = *(const float4*)&sXt[k*PAD + ty*4];
        float4 wqc = *(const float4*)&sWq[k*PAD + tx*4];
        float4 wvc = *(const float4*)&sWv[k*PAD + tx*4];
        float xa[4]  = {xr.x, xr.y, xr.z, xr.w};
        float wqa[4] = {wqc.x, wqc.y, wqc.z, wqc.w};
        float wva[4] = {wvc.x, wvc.y, wvc.z, wvc.w};
        #pragma unroll
        for (int i = 0; i < 4; i++)
            #pragma unroll
            for (int j = 0; j < 4; j++) {
                qa[i][j] += xa[i] * wqa[j];
                va[i][j] += xa[i] * wva[j];
            }
    }

    float4 bq4 = *(const float4*)&bq[tx*4];
    float4 bv4 = *(const float4*)&bv[tx*4];
    float bqa[4] = {bq4.x, bq4.y, bq4.z, bq4.w};
    float bva[4] = {bv4.x, bv4.y, bv4.z, bv4.w};

    #pragma unroll
    for (int i = 0; i < 4; i++) {
        int s = s0 + ty*4 + i;
        unsigned base = (unsigned)((b*N_ + s)*32 + tx*2);
        g_q16[base]   = pack2h(qa[i][0]+bqa[0], qa[i][1]+bqa[1]);
        g_q16[base+1] = pack2h(qa[i][2]+bqa[2], qa[i][3]+bqa[3]);
        g_v16[base]   = pack2h(va[i][0]+bva[0], va[i][1]+bva[1]);
        g_v16[base+1] = pack2h(va[i][2]+bva[2], va[i][3]+bva[3]);
    }
}

// vsum[b][d] = sum_s v16[b][s][d]  (fp32 accumulate, matches SV operand)
__global__ __launch_bounds__(512) void vsum_kernel()
{
    int b = blockIdx.x, tid = threadIdx.x;
    int d = tid & 63, chunk = tid >> 6;       // 8 chunks of 512 rows
    int w = d >> 1, hi = d & 1;
    __shared__ float red[512];
    float acc = 0.f;
    for (int s = chunk*512; s < chunk*512 + 512; s++) {
        unsigned wv_ = g_v16[(b*N_ + s)*32 + w];
        __half2 h2 = *reinterpret_cast<__half2*>(&wv_);
        acc += hi ? __half2float(h2.y) : __half2float(h2.x);
    }
    red[tid] = acc;
    __syncthreads();
    if (chunk == 0) {
        float s = 0.f;
        #pragma unroll
        for (int k = 0; k < 8; k++) s += red[d + 64*k];
        g_vsum[b*64 + d] = s;
    }
}

// ---------------------------------------------------------------------------
// HMMA fp16 sigmoid attention, double-buffered cp.async, fused epilogue.
// o = sum (sig(qk/8)-0.5) v + 0.5 vsum
// QK: 1 fp16 term.  SV: (s-0.5) fp16 x V fp16, 1 term.
// ---------------------------------------------------------------------------
#define QH_OFF 0
#define BUF0 16384
#define BUFSZ 32768            // K 16K | V 16K
#define ATT_SMEM (16384 + 2*BUFSZ)   // 81920

__device__ __forceinline__ void load_tile(uint32_t sbuf, int b, int mt, int tid)
{
    const char* pQ = (const char*)g_q16;
    const char* pV = (const char*)g_v16;
    #pragma unroll
    for (int j = 0; j < 8; j++) {
        const char* src = (j < 4) ? pQ : pV;
        int rem = tid + (j & 3)*256;            // 0..1023
        int r = rem >> 3, c = (rem & 7)*16;
        // row stride = 64 fp16 = 128 bytes
        cpa16(sbuf + (uint32_t)((j >> 2)*16384 + r*128 + (c ^ ((r & 7) << 4))),
              src + (size_t)(b*N_ + mt + r)*128 + c);
    }
}

__global__ __launch_bounds__(256, 1) void attn_mma()
{
    extern __shared__ char smem[];
    const uint32_t sb = smem_u32(smem);
    const int tid = threadIdx.x, lane = tid & 31, wid = tid >> 5;
    const int wm = wid >> 1, wn = wid & 1;
    const int b = blockIdx.y, s0 = blockIdx.x * 128;
    const int g = lane >> 3, rr = lane & 7;

    // prologue: Q tile + K/V tile 0, one cp.async group
    {
        const char* pQ = (const char*)g_q16;
        #pragma unroll
        for (int j = 0; j < 4; j++) {
            int rem = tid + j*256;
            int r = rem >> 3, c = (rem & 7)*16;
            cpa16(sb + QH_OFF + (uint32_t)(r*128 + (c ^ ((r & 7) << 4))),
                  pQ + (size_t)(b*N_ + s0 + r)*128 + c);
        }
    }
    load_tile(sb + BUF0, b, 0, tid);
    CP_COMMIT();

    uint32_t qf[2][4][4];         // Q fragments [mi][kk][4], live whole kernel
    float oacc[2][8][4];
    #pragma unroll
    for (int mi = 0; mi < 2; mi++)
        #pragma unroll
        for (int j = 0; j < 8; j++)
            #pragma unroll
            for (int q = 0; q < 4; q++) oacc[mi][j][q] = 0.f;

    for (int t = 0; t < 32; t++) {
        if (t < 31) {
            load_tile(sb + BUF0 + (uint32_t)(((t+1) & 1)*BUFSZ), b, (t+1) << 7, tid);
            CP_COMMIT();
            asm volatile("cp.async.wait_group 1;" ::: "memory");
        } else {
            asm volatile("cp.async.wait_group 0;" ::: "memory");
        }
        __syncthreads();

        const uint32_t kb = sb + BUF0 + (uint32_t)((t & 1)*BUFSZ);

        if (t == 0) {
            #pragma unroll
            for (int kk = 0; kk < 4; kk++)
                #pragma unroll
                for (int mi = 0; mi < 2; mi++) {
                    int row = wm*32 + mi*16 + rr + ((g & 1) << 3);
                    uint32_t cb = (uint32_t)(kk*32 + ((g >> 1) << 4));
                    ldsm4(qf[mi][kk], sb + QH_OFF + (uint32_t)(row*128) + (cb ^ ((row & 7) << 4)));
                }
        }

        // fused: per 16-key group -> QK(1 term), sigmoid, SV(1 term)
        #pragma unroll
        for (int p = 0; p < 4; p++) {
            float sacc[2][2][4];
            #pragma unroll
            for (int mi = 0; mi < 2; mi++)
                #pragma unroll
                for (int jj = 0; jj < 2; jj++)
                    #pragma unroll
                    for (int q = 0; q < 4; q++) sacc[mi][jj][q] = 0.f;

            #pragma unroll
            for (int kk = 0; kk < 4; kk++) {
                int key = wn*64 + p*16 + rr + ((g >> 1) << 3);
                uint32_t cb = (uint32_t)(kk*32 + ((g & 1) << 4));
                uint32_t ad = kb + (uint32_t)(key*128) + (cb ^ ((key & 7) << 4));
                uint32_t bk[4];
                ldsm4(bk, ad);                // K
                #pragma unroll
                for (int mi = 0; mi < 2; mi++) {
                    mma16816(sacc[mi][0], qf[mi][kk], bk[0], bk[1]);
                    mma16816(sacc[mi][1], qf[mi][kk], bk[2], bk[3]);
                }
            }

            // centered sigmoid, saturation-safe: sig(x/8) - 0.5
            uint32_t as_[2][4];
            #pragma unroll
            for (int mi = 0; mi < 2; mi++) {
                #pragma unroll
                for (int jj = 0; jj < 2; jj++)
                    #pragma unroll
                    for (int q = 0; q < 4; q++) {
                        float e = __expf(-0.125f * sacc[mi][jj][q]);
                        sacc[mi][jj][q] = __fdividef(1.f, 1.f + e) - 0.5f;
                    }
                as_[mi][0] = pack2h(sacc[mi][0][0], sacc[mi][0][1]);
                as_[mi][1] = pack2h(sacc[mi][0][2], sacc[mi][0][3]);
                as_[mi][2] = pack2h(sacc[mi][1][0], sacc[mi][1][1]);
                as_[mi][3] = pack2h(sacc[mi][1][2], sacc[mi][1][3]);
            }

            #pragma unroll
            for (int dp = 0; dp < 4; dp++) {
                int key = wn*64 + p*16 + rr + ((g & 1) << 3);
                uint32_t cb = (uint32_t)(dp*32 + ((g >> 1) << 4));
                uint32_t ad = kb + 16384u + (uint32_t)(key*128) + (cb ^ ((key & 7) << 4));
                uint32_t vv[4];
                ldsm4t(vv, ad);               // V (transposed)
                #pragma unroll
                for (int mi = 0; mi < 2; mi++) {
                    mma16816(oacc[mi][2*dp],   as_[mi], vv[0], vv[1]);
                    mma16816(oacc[mi][2*dp+1], as_[mi], vv[2], vv[3]);
                }
            }
        }
        __syncthreads();   // all reads of buf[t&1] done before next overwrite
    }

    // ---- cross-warp_n reduction + vsum correction + writeout ----
    float* ored = (float*)(smem + BUF0);      // 128x64 fp32, 32KB
    if (wn == 1) {
        #pragma unroll
        for (int mi = 0; mi < 2; mi++)
            #pragma unroll
            for (int dj = 0; dj < 8; dj++) {
                int row = wm*32 + mi*16 + (lane >> 2);
                int col = dj*8 + (lane & 3)*2;
                *(float2*)&ored[row*64 + col]     = make_float2(oacc[mi][dj][0], oacc[mi][dj][1]);
                *(float2*)&ored[(row+8)*64 + col] = make_float2(oacc[mi][dj][2], oacc[mi][dj][3]);
            }
    }
    __syncthreads();
    if (wn == 0) {
        #pragma unroll
        for (int mi = 0; mi < 2; mi++)
            #pragma unroll
            for (int dj = 0; dj < 8; dj++) {
                int row = wm*32 + mi*16 + (lane >> 2);
                int col = dj*8 + (lane & 3)*2;
                float vs0 = 0.5f * g_vsum[b*64 + col];
                float vs1 = 0.5f * g_vsum[b*64 + col + 1];
                float2 p0 = *(float2*)&ored[row*64 + col];
                float2 p1 = *(float2*)&ored[(row+8)*64 + col];
                *(float2*)&g_o[(size_t)(b*N_ + s0 + row)*64 + col] =
                    make_float2(oacc[mi][dj][0] + p0.x + vs0, oacc[mi][dj][1] + p0.y + vs1);
                *(float2*)&g_o[(size_t)(b*N_ + s0 + row + 8)*64 + col] =
                    make_float2(oacc[mi][dj][2] + p1.x + vs0, oacc[mi][dj][3] + p1.y + vs1);
            }
    }
}

// ---------------------------------------------------------------------------
__global__ void x1_kernel(const float* __restrict__ feature,
                          const float* __restrict__ hgate)
{
    int idx = blockIdx.x * blockDim.x + threadIdx.x;
    if (idx >= ELEMS) return;
    float hg = hgate[0];
    int c = idx & 63, w = (idx >> 6) & 63, h = (idx >> 12) & 63, b = idx >> 18;
    g_x1[idx] = feature[idx] + hg * g_o[(b*N_ + w*64 + c)*D_ + h];
}

__global__ void p_kernel(const float* __restrict__ predict,
                         const float* __restrict__ cw,
                         const float* __restrict__ cb)
{
    int pix = blockIdx.x * blockDim.x + threadIdx.x;
    if (pix >= B_*HW_) return;
    float acc = cb[0];
    #pragma unroll
    for (int k = 0; k < NC_; k++)
        acc += (1.f - sigmoidf_(predict[pix*NC_ + k])) * cw[k];
    g_p[pix] = acc;
}

__global__ void final_kernel(const float* __restrict__ feature,
                             const float* __restrict__ wgate,
                             float* __restrict__ out)
{
    int idx = blockIdx.x * blockDim.x + threadIdx.x;
    if (idx >= ELEMS) return;
    float wg = wgate[0];
    int c = idx & 63, w = (idx >> 6) & 63, h = (idx >> 12) & 63, b = idx >> 18;
    float attw = g_o[(b*N_ + h*64 + c)*D_ + w];
    out[idx] = g_p[idx >> 6] * (feature[idx] + g_x1[idx] + wg * attw);
}

extern "C" void kernel_launch(void* const* d_in, const int* in_sizes, int n_in,
                              void* d_out, int out_size)
{
    const float* feature = (const float*)d_in[0];
    const float* predict = (const float*)d_in[1];
    const float* hq_w = (const float*)d_in[2];
    const float* hq_b = (const float*)d_in[3];
    const float* hv_w = (const float*)d_in[4];
    const float* hv_b = (const float*)d_in[5];
    const float* wq_w = (const float*)d_in[6];
    const float* wq_b = (const float*)d_in[7];
    const float* wv_w = (const float*)d_in[8];
    const float* wv_b = (const float*)d_in[9];
    const float* h_gate = (const float*)d_in[10];
    const float* w_gate = (const float*)d_in[11];
    const float* conv_w = (const float*)d_in[12];
    const float* conv_b = (const float*)d_in[13];
    float* out = (float*)d_out;

    const int qv_smem = 3 * D_ * PAD * (int)sizeof(float);
    cudaFuncSetAttribute(qv_kernel<0>, cudaFuncAttributeMaxDynamicSharedMemorySize, qv_smem);
    cudaFuncSetAttribute(qv_kernel<1>, cudaFuncAttributeMaxDynamicSharedMemorySize, qv_smem);
    cudaFuncSetAttribute(attn_mma, cudaFuncAttributeMaxDynamicSharedMemorySize, ATT_SMEM);

    dim3 gqv(N_/64, B_);
    dim3 gat(N_/128, B_);

    // Pass 1: height attention
    qv_kernel<0><<<gqv, 256, qv_smem>>>(feature, hq_w, hq_b, hv_w, hv_b);
    vsum_kernel<<<B_, 512>>>();
    attn_mma<<<gat, 256, ATT_SMEM>>>();
    x1_kernel<<<ELEMS/256, 256>>>(feature, h_gate);

    // Pass 2: width attention
    qv_kernel<1><<<gqv, 256, qv_smem>>>(nullptr, wq_w, wq_b, wv_w, wv_b);
    vsum_kernel<<<B_, 512>>>();
    attn_mma<<<gat, 256, ATT_SMEM>>>();

    // Gate + output
    p_kernel<<<(B_*HW_ + 255)/256, 256>>>(predict, conv_w, conv_b);
    final_kernel<<<ELEMS/256, 256>>>(feature, w_gate, out);
}

// round 9
// speedup vs baseline: 10.6904x; 1.6413x over previous
#include <cuda_runtime.h>
#include <cuda_fp16.h>
#include <cstdint>

#define B_ 4
#define N_ 4096
#define D_ 64
#define PAD 68
#define HW_ (64*64)
#define ELEMS (B_*64*64*64)
#define NC_ 19

// Scratch
__device__ float g_ot1[B_*D_*N_];     // height-attn O, transposed [b][d][s]
__device__ float g_ot2[B_*D_*N_];     // width-attn  O, transposed [b][d][s]
__device__ float g_vpart[B_*64*64];   // per-CTA column partial sums of v' = 0.5v
// fp16 operands, packed half2 words, natural layout [b][s][d]; v stores 0.5*v
__device__ __align__(128) unsigned g_q16[B_*N_*D_/2];
__device__ __align__(128) unsigned g_v16[B_*N_*D_/2];

// ---------------------------------------------------------------------------
__device__ __forceinline__ float sigmoidf_(float x) {
    return __fdividef(1.f, 1.f + __expf(-x));
}
__device__ __forceinline__ uint32_t smem_u32(const void* p) {
    uint32_t a;
    asm("{ .reg .u64 t; cvta.to.shared.u64 t, %1; cvt.u32.u64 %0, t; }" : "=r"(a) : "l"(p));
    return a;
}
__device__ __forceinline__ unsigned pack2h(float a, float b) {
    __half2 h = __floats2half2_rn(a, b);
    return *reinterpret_cast<unsigned*>(&h);
}
__device__ __forceinline__ float tanh_ap(float x) {
    float y;
    asm("tanh.approx.f32 %0, %1;" : "=f"(y) : "f"(x));
    return y;
}
__device__ __forceinline__ void ldsm4(uint32_t* r, uint32_t addr) {
    asm volatile("ldmatrix.sync.aligned.m8n8.x4.shared.b16 {%0,%1,%2,%3}, [%4];"
                 : "=r"(r[0]), "=r"(r[1]), "=r"(r[2]), "=r"(r[3]) : "r"(addr));
}
__device__ __forceinline__ void ldsm4t(uint32_t* r, uint32_t addr) {
    asm volatile("ldmatrix.sync.aligned.m8n8.x4.trans.shared.b16 {%0,%1,%2,%3}, [%4];"
                 : "=r"(r[0]), "=r"(r[1]), "=r"(r[2]), "=r"(r[3]) : "r"(addr));
}
__device__ __forceinline__ void mma16816(float* c, const uint32_t* a,
                                         uint32_t b0, uint32_t b1) {
    asm volatile("mma.sync.aligned.m16n8k16.row.col.f32.f16.f16.f32 "
                 "{%0,%1,%2,%3}, {%4,%5,%6,%7}, {%8,%9}, {%0,%1,%2,%3};"
                 : "+f"(c[0]), "+f"(c[1]), "+f"(c[2]), "+f"(c[3])
                 : "r"(a[0]), "r"(a[1]), "r"(a[2]), "r"(a[3]), "r"(b0), "r"(b1));
}
__device__ __forceinline__ void cpa16(uint32_t s, const void* g) {
    asm volatile("cp.async.cg.shared.global [%0], [%1], 16;"
                 :: "r"(s), "l"(__cvta_generic_to_global(g)) : "memory");
}
#define CP_COMMIT() asm volatile("cp.async.commit_group;" ::: "memory")

// ---------------------------------------------------------------------------
// q/v projection -> fp16 (v scaled by 0.5), plus vsum column partials.
// LAYOUT 0: x[b,s,d] = feature[b,d,w,c], s=w*64+c (w const per block, c=r)
// LAYOUT 1: x[b,s,d] = feature[b,h,d,c] + hg*Ot1[b][h][d*64+c]  (x1 inline)
// ---------------------------------------------------------------------------
template<int LAYOUT>
__global__ __launch_bounds__(256) void qv_kernel(
    const float* __restrict__ src,
    const float* __restrict__ wq, const float* __restrict__ bq,
    const float* __restrict__ wv, const float* __restrict__ bv,
    const float* __restrict__ gate)
{
    extern __shared__ float sm[];
    float* sXt = sm;
    float* sWq = sm + D_*PAD;
    float* sWv = sm + 2*D_*PAD;

    int b = blockIdx.y, s0 = blockIdx.x * 64, tid = threadIdx.x;
    int hw0 = s0 >> 6;                 // w (layout0) or h (layout1), const per block

    for (int i = tid; i < 64*16; i += 256) {
        int k = i >> 4, c4 = (i & 15) * 4;
        *(float4*)&sWq[k*PAD + c4] = *(const float4*)&wq[k*64 + c4];
        *(float4*)&sWv[k*PAD + c4] = *(const float4*)&wv[k*64 + c4];
    }
    if (LAYOUT == 0) {
        for (int i = tid; i < 64*64; i += 256) {
            int d = i >> 6, r = i & 63;
            sXt[d*PAD + r] = src[((b*64 + d)*64 + hw0)*64 + r];
        }
    } else {
        float hg = gate[0];
        for (int i = tid; i < 64*64; i += 256) {
            int d = i >> 6, r = i & 63;
            float fv = src[((b*64 + hw0)*64 + d)*64 + r];
            float ov = g_ot1[(size_t)(b*64 + hw0)*4096 + d*64 + r];
            sXt[d*PAD + r] = fv + hg * ov;
        }
    }
    __syncthreads();

    int ty = tid >> 4, tx = tid & 15;
    float qa[4][4] = {{0.f}}, va[4][4] = {{0.f}};

    #pragma unroll 4
    for (int k = 0; k < 64; k++) {
        float4 xr  = *(const float4*)&sXt[k*PAD + ty*4];
        float4 wqc = *(const float4*)&sWq[k*PAD + tx*4];
        float4 wvc = *(const float4*)&sWv[k*PAD + tx*4];
        float xa[4]  = {xr.x, xr.y, xr.z, xr.w};
        float wqa[4] = {wqc.x, wqc.y, wqc.z, wqc.w};
        float wva[4] = {wvc.x, wvc.y, wvc.z, wvc.w};
        #pragma unroll
        for (int i = 0; i < 4; i++)
            #pragma unroll
            for (int j = 0; j < 4; j++) {
                qa[i][j] += xa[i] * wqa[j];
                va[i][j] += xa[i] * wva[j];
            }
    }

    float4 bq4 = *(const float4*)&bq[tx*4];
    float4 bv4 = *(const float4*)&bv[tx*4];
    float bqa[4] = {bq4.x, bq4.y, bq4.z, bq4.w};
    float bva[4] = {bv4.x, bv4.y, bv4.z, bv4.w};

    #pragma unroll
    for (int i = 0; i < 4; i++) {
        int s = s0 + ty*4 + i;
        unsigned base = (unsigned)((b*N_ + s)*32 + tx*2);
        g_q16[base]   = pack2h(qa[i][0]+bqa[0], qa[i][1]+bqa[1]);
        g_q16[base+1] = pack2h(qa[i][2]+bqa[2], qa[i][3]+bqa[3]);
        // v' = 0.5 v
        g_v16[base]   = pack2h(0.5f*(va[i][0]+bva[0]), 0.5f*(va[i][1]+bva[1]));
        g_v16[base+1] = pack2h(0.5f*(va[i][2]+bva[2]), 0.5f*(va[i][3]+bva[3]));
    }

    // column partial sums of v' over this block's 64 rows (fp32 exact)
    float vs[4];
    #pragma unroll
    for (int j = 0; j < 4; j++)
        vs[j] = 0.5f*(va[0][j] + va[1][j] + va[2][j] + va[3][j] + 4.f*bva[j]);
    __syncthreads();
    #pragma unroll
    for (int j = 0; j < 4; j++) sm[ty*64 + tx*4 + j] = vs[j];
    __syncthreads();
    if (tid < 64) {
        float acc = 0.f;
        #pragma unroll
        for (int k = 0; k < 16; k++) acc += sm[k*64 + tid];
        g_vpart[(b*64 + blockIdx.x)*64 + tid] = acc;
    }
}

// ---------------------------------------------------------------------------
// HMMA fp16 sigmoid attention, double-buffered cp.async.
// o = sum tanh(qk/16) * v' + sum v'     (v' = 0.5 v;  s-0.5 = 0.5 tanh(x/16))
// Output written TRANSPOSED: dst[b][d][s].
// ---------------------------------------------------------------------------
#define QH_OFF 0
#define BUF0 16384
#define BUFSZ 32768                 // K 16K | V 16K
#define SVS_OFF (16384 + 2*BUFSZ)   // 81920: 64-float vsum cache
#define ATT_SMEM (SVS_OFF + 256)    // 82176
#define OPITCH 65                   // fp32 transpose pitch (conflict-free)

__device__ __forceinline__ void load_tile(uint32_t sbuf, int b, int mt, int tid)
{
    const char* pQ = (const char*)g_q16;
    const char* pV = (const char*)g_v16;
    #pragma unroll
    for (int j = 0; j < 8; j++) {
        const char* src = (j < 4) ? pQ : pV;
        int rem = tid + (j & 3)*256;
        int r = rem >> 3, c = (rem & 7)*16;
        cpa16(sbuf + (uint32_t)((j >> 2)*16384 + r*128 + (c ^ ((r & 7) << 4))),
              src + (size_t)(b*N_ + mt + r)*128 + c);
    }
}

template<int PASS>
__global__ __launch_bounds__(256, 1) void attn_mma()
{
    extern __shared__ char smem[];
    const uint32_t sb = smem_u32(smem);
    const int tid = threadIdx.x, lane = tid & 31, wid = tid >> 5;
    const int wm = wid >> 1, wn = wid & 1;
    const int b = blockIdx.y, s0 = blockIdx.x * 128;
    const int g = lane >> 3, rr = lane & 7;
    float* dst = (PASS == 0) ? g_ot1 : g_ot2;

    // prologue: Q tile + K/V tile 0
    {
        const char* pQ = (const char*)g_q16;
        #pragma unroll
        for (int j = 0; j < 4; j++) {
            int rem = tid + j*256;
            int r = rem >> 3, c = (rem & 7)*16;
            cpa16(sb + QH_OFF + (uint32_t)(r*128 + (c ^ ((r & 7) << 4))),
                  pQ + (size_t)(b*N_ + s0 + r)*128 + c);
        }
    }
    load_tile(sb + BUF0, b, 0, tid);
    CP_COMMIT();

    // reduce vsum partials into smem while tile 0 is in flight
    if (tid < 64) {
        float a = 0.f;
        #pragma unroll
        for (int k = 0; k < 64; k++) a += g_vpart[(b*64 + k)*64 + tid];
        ((float*)(smem + SVS_OFF))[tid] = a;
    }

    uint32_t qf[2][4][4];
    float oacc[2][8][4];
    #pragma unroll
    for (int mi = 0; mi < 2; mi++)
        #pragma unroll
        for (int j = 0; j < 8; j++)
            #pragma unroll
            for (int q = 0; q < 4; q++) oacc[mi][j][q] = 0.f;

    for (int t = 0; t < 32; t++) {
        if (t < 31) {
            load_tile(sb + BUF0 + (uint32_t)(((t+1) & 1)*BUFSZ), b, (t+1) << 7, tid);
            CP_COMMIT();
            asm volatile("cp.async.wait_group 1;" ::: "memory");
        } else {
            asm volatile("cp.async.wait_group 0;" ::: "memory");
        }
        __syncthreads();

        const uint32_t kb = sb + BUF0 + (uint32_t)((t & 1)*BUFSZ);

        if (t == 0) {
            #pragma unroll
            for (int kk = 0; kk < 4; kk++)
                #pragma unroll
                for (int mi = 0; mi < 2; mi++) {
                    int row = wm*32 + mi*16 + rr + ((g & 1) << 3);
                    uint32_t cb = (uint32_t)(kk*32 + ((g >> 1) << 4));
                    ldsm4(qf[mi][kk], sb + QH_OFF + (uint32_t)(row*128) + (cb ^ ((row & 7) << 4)));
                }
        }

        #pragma unroll
        for (int p = 0; p < 4; p++) {
            float sacc[2][2][4];
            #pragma unroll
            for (int mi = 0; mi < 2; mi++)
                #pragma unroll
                for (int jj = 0; jj < 2; jj++)
                    #pragma unroll
                    for (int q = 0; q < 4; q++) sacc[mi][jj][q] = 0.f;

            #pragma unroll
            for (int kk = 0; kk < 4; kk++) {
                int key = wn*64 + p*16 + rr + ((g >> 1) << 3);
                uint32_t cb = (uint32_t)(kk*32 + ((g & 1) << 4));
                uint32_t ad = kb + (uint32_t)(key*128) + (cb ^ ((key & 7) << 4));
                uint32_t bk[4];
                ldsm4(bk, ad);
                #pragma unroll
                for (int mi = 0; mi < 2; mi++) {
                    mma16816(sacc[mi][0], qf[mi][kk], bk[0], bk[1]);
                    mma16816(sacc[mi][1], qf[mi][kk], bk[2], bk[3]);
                }
            }

            // s-0.5 = 0.5*tanh(x/16); 0.5 folded into v'. A operand = tanh(x/16)
            uint32_t as_[2][4];
            #pragma unroll
            for (int mi = 0; mi < 2; mi++) {
                #pragma unroll
                for (int jj = 0; jj < 2; jj++)
                    #pragma unroll
                    for (int q = 0; q < 4; q++)
                        sacc[mi][jj][q] = tanh_ap(sacc[mi][jj][q] * 0.0625f);
                as_[mi][0] = pack2h(sacc[mi][0][0], sacc[mi][0][1]);
                as_[mi][1] = pack2h(sacc[mi][0][2], sacc[mi][0][3]);
                as_[mi][2] = pack2h(sacc[mi][1][0], sacc[mi][1][1]);
                as_[mi][3] = pack2h(sacc[mi][1][2], sacc[mi][1][3]);
            }

            #pragma unroll
            for (int dp = 0; dp < 4; dp++) {
                int key = wn*64 + p*16 + rr + ((g & 1) << 3);
                uint32_t cb = (uint32_t)(dp*32 + ((g >> 1) << 4));
                uint32_t ad = kb + 16384u + (uint32_t)(key*128) + (cb ^ ((key & 7) << 4));
                uint32_t vv[4];
                ldsm4t(vv, ad);
                #pragma unroll
                for (int mi = 0; mi < 2; mi++) {
                    mma16816(oacc[mi][2*dp],   as_[mi], vv[0], vv[1]);
                    mma16816(oacc[mi][2*dp+1], as_[mi], vv[2], vv[3]);
                }
            }
        }
        __syncthreads();
    }

    // ---- reduce across wn, add vsum, write TRANSPOSED dst[b][col][s0+row] ----
    float* ored = (float*)(smem + BUF0);      // [128][OPITCH]
    if (wn == 1) {
        #pragma unroll
        for (int mi = 0; mi < 2; mi++)
            #pragma unroll
            for (int dj = 0; dj < 8; dj++) {
                int row = wm*32 + mi*16 + (lane >> 2);
                int col = dj*8 + (lane & 3)*2;
                ored[row*OPITCH + col]       = oacc[mi][dj][0];
                ored[row*OPITCH + col + 1]   = oacc[mi][dj][1];
                ored[(row+8)*OPITCH + col]   = oacc[mi][dj][2];
                ored[(row+8)*OPITCH + col+1] = oacc[mi][dj][3];
            }
    }
    __syncthreads();
    if (wn == 0) {
        #pragma unroll
        for (int mi = 0; mi < 2; mi++)
            #pragma unroll
            for (int dj = 0; dj < 8; dj++) {
                int row = wm*32 + mi*16 + (lane >> 2);
                int col = dj*8 + (lane & 3)*2;
                ored[row*OPITCH + col]       += oacc[mi][dj][0];
                ored[row*OPITCH + col + 1]   += oacc[mi][dj][1];
                ored[(row+8)*OPITCH + col]   += oacc[mi][dj][2];
                ored[(row+8)*OPITCH + col+1] += oacc[mi][dj][3];
            }
    }
    __syncthreads();
    const float* svs = (const float*)(smem + SVS_OFF);
    for (int i = tid; i < 8192; i += 256) {
        int col = i >> 7, row = i & 127;
        dst[(size_t)(b*64 + col)*4096 + s0 + row] = ored[row*OPITCH + col] + svs[col];
    }
}

// ---------------------------------------------------------------------------
// out = p * (2*feature + hg*oh + wg*ow), p fused per-pixel.
// oh = Ot1[b][h][w*64+c], ow = Ot2[b][w][h*64+c]
// ---------------------------------------------------------------------------
__global__ __launch_bounds__(256) void final_kernel(
    const float* __restrict__ feature, const float* __restrict__ predict,
    const float* __restrict__ cw, const float* __restrict__ cb,
    const float* __restrict__ hgate, const float* __restrict__ wgate,
    float* __restrict__ out)
{
    __shared__ float sp[4];
    int tid = threadIdx.x;
    int idx = blockIdx.x * 256 + tid;
    if (tid < 4) {
        int pix = blockIdx.x * 4 + tid;
        float acc = cb[0];
        #pragma unroll
        for (int k = 0; k < NC_; k++)
            acc += (1.f - sigmoidf_(predict[pix*NC_ + k])) * cw[k];
        sp[tid] = acc;
    }
    __syncthreads();
    float hg = hgate[0], wg = wgate[0];
    int c = idx & 63, w = (idx >> 6) & 63, h = (idx >> 12) & 63, b = idx >> 18;
    float oh = g_ot1[(size_t)(b*64 + h)*4096 + w*64 + c];
    float ow = g_ot2[(size_t)(b*64 + w)*4096 + h*64 + c];
    out[idx] = sp[tid >> 6] * (2.f*feature[idx] + hg*oh + wg*ow);
}

extern "C" void kernel_launch(void* const* d_in, const int* in_sizes, int n_in,
                              void* d_out, int out_size)
{
    const float* feature = (const float*)d_in[0];
    const float* predict = (const float*)d_in[1];
    const float* hq_w = (const float*)d_in[2];
    const float* hq_b = (const float*)d_in[3];
    const float* hv_w = (const float*)d_in[4];
    const float* hv_b = (const float*)d_in[5];
    const float* wq_w = (const float*)d_in[6];
    const float* wq_b = (const float*)d_in[7];
    const float* wv_w = (const float*)d_in[8];
    const float* wv_b = (const float*)d_in[9];
    const float* h_gate = (const float*)d_in[10];
    const float* w_gate = (const float*)d_in[11];
    const float* conv_w = (const float*)d_in[12];
    const float* conv_b = (const float*)d_in[13];
    float* out = (float*)d_out;

    const int qv_smem = 3 * D_ * PAD * (int)sizeof(float);
    cudaFuncSetAttribute(qv_kernel<0>, cudaFuncAttributeMaxDynamicSharedMemorySize, qv_smem);
    cudaFuncSetAttribute(qv_kernel<1>, cudaFuncAttributeMaxDynamicSharedMemorySize, qv_smem);
    cudaFuncSetAttribute(attn_mma<0>, cudaFuncAttributeMaxDynamicSharedMemorySize, ATT_SMEM);
    cudaFuncSetAttribute(attn_mma<1>, cudaFuncAttributeMaxDynamicSharedMemorySize, ATT_SMEM);

    dim3 gqv(N_/64, B_);
    dim3 gat(N_/128, B_);

    // Pass 1: height attention
    qv_kernel<0><<<gqv, 256, qv_smem>>>(feature, hq_w, hq_b, hv_w, hv_b, nullptr);
    attn_mma<0><<<gat, 256, ATT_SMEM>>>();

    // Pass 2: width attention (x1 composed inline from feature + h_gate*Ot1)
    qv_kernel<1><<<gqv, 256, qv_smem>>>(feature, wq_w, wq_b, wv_w, wv_b, h_gate);
    attn_mma<1><<<gat, 256, ATT_SMEM>>>();

    // Fused gate + output
    final_kernel<<<ELEMS/256, 256>>>(feature, predict, conv_w, conv_b,
                                     h_gate, w_gate, out);
}